// round 8
// baseline (speedup 1.0000x reference)
#include <cuda_runtime.h>
#include <cuda_fp16.h>
#include <cstdint>

#define BB 256
#define TT 2000
#define II 23
#define HH 128
#define G3 384
#define MB 8                   // batches per rec CTA
#define NREC_CTAS (BB / MB)    // 32
#define WPB 16                 // warps per rec CTA
#define HSTRIDE 136            // padded fp16 h-row stride (272B)
#define TCH 100
#define NCH (TT / TCH)

// gx scratch in FRAGMENT layout (16-warp rec mapping), fp16x2 words:
// byte offset(t, cta, warp16, gate, lane) =
//   t*196608 + cta*6144 + warp16*384 + gate*128 + lane*4
// lane = g*4 + tig ; halves = (col, col+1), col = warp16*8 + 2*tig
#define GX_TSTEP 196608u
__device__ uint32_t g_gx2[(size_t)TT * NREC_CTAS * WPB * 96];

// ---- helpers ----
__device__ __forceinline__ unsigned long long fma2(unsigned long long a,
                                                   unsigned long long b,
                                                   unsigned long long c) {
    unsigned long long d;
    asm("fma.rn.f32x2 %0, %1, %2, %3;" : "=l"(d) : "l"(a), "l"(b), "l"(c));
    return d;
}
__device__ __forceinline__ unsigned long long pack2(float lo, float hi) {
    unsigned long long d;
    asm("mov.b64 %0, {%1, %2};" : "=l"(d) : "f"(lo), "f"(hi));
    return d;
}
__device__ __forceinline__ void unpack2(unsigned long long v, float& lo, float& hi) {
    asm("mov.b64 {%0, %1}, %2;" : "=f"(lo), "=f"(hi) : "l"(v));
}
__device__ __forceinline__ float tanh_ap(float x) {
    float y;
    asm("tanh.approx.f32 %0, %1;" : "=f"(y) : "f"(x));
    return y;
}
__device__ __forceinline__ float sigmoid_ap(float x) {
    return fmaf(tanh_ap(0.5f * x), 0.5f, 0.5f);
}
__device__ __forceinline__ uint32_t pack_h2(float lo, float hi) {
    uint32_t d;
    asm("cvt.rn.f16x2.f32 %0, %1, %2;" : "=r"(d) : "f"(hi), "f"(lo));
    return d;
}
__device__ __forceinline__ float h2_lo(uint32_t v) {
    return __half2float(__low2half(*reinterpret_cast<const __half2*>(&v)));
}
__device__ __forceinline__ float h2_hi(uint32_t v) {
    return __half2float(__high2half(*reinterpret_cast<const __half2*>(&v)));
}
__device__ __forceinline__ void ldsm_x2(uint32_t& r0, uint32_t& r1, uint32_t addr) {
    asm volatile("ldmatrix.sync.aligned.m8n8.x2.shared.b16 {%0,%1}, [%2];"
                 : "=r"(r0), "=r"(r1) : "r"(addr));
}
__device__ __forceinline__ void mma_f16(float& d0, float& d1, float& d2, float& d3,
                                        uint32_t a0, uint32_t a1, uint32_t a2, uint32_t a3,
                                        uint32_t b0, uint32_t b1,
                                        float c0, float c1, float c2, float c3) {
    asm volatile(
        "mma.sync.aligned.m16n8k16.row.col.f32.f16.f16.f32 "
        "{%0,%1,%2,%3},{%4,%5,%6,%7},{%8,%9},{%10,%11,%12,%13};"
        : "=f"(d0), "=f"(d1), "=f"(d2), "=f"(d3)
        : "r"(a0), "r"(a1), "r"(a2), "r"(a3), "r"(b0), "r"(b1),
          "f"(c0), "f"(c1), "f"(c2), "f"(c3));
}

// ============================================================
// Phase 1: gx = W_ih.x + b_ih, fragment layout (f16x2).
// ============================================================
__global__ __launch_bounds__(G3) void gx_kernel(
    const float* __restrict__ x,
    const float* __restrict__ Wih,
    const float* __restrict__ bih)
{
    const int b   = blockIdx.y;
    const int t0g = blockIdx.x * TCH;
    const int r   = threadIdx.x;

    __shared__ __align__(16) float xt[II][TCH + 8];

    const float* xbase = x + ((size_t)b * TT + t0g) * II;
    for (int e = r; e < TCH * II; e += G3) {
        int t = e / II;
        int k = e - t * II;
        xt[k][t] = xbase[e];
    }

    unsigned long long ww[II];
#pragma unroll
    for (int k = 0; k < II; k++) {
        float wv = Wih[r * II + k];
        ww[k] = pack2(wv, wv);
    }
    const float bv = bih[r];
    const unsigned long long bp = pack2(bv, bv);

    // fragment-layout address for row r, batch b (16-warp mapping)
    const int gate = r >> 7;
    const int col  = r & 127;
    const int w16  = col >> 3;
    const int tig  = (col & 7) >> 1;
    const int cta  = b >> 3;
    const int g    = b & 7;
    const uint32_t inoff = (uint32_t)(cta * 6144 + w16 * 384 + gate * 128 +
                                      (g * 4 + tig) * 4);
    char* gxb = reinterpret_cast<char*>(g_gx2);
    const bool writer = ((r & 1) == 0);

    __syncthreads();

    for (int t0 = 0; t0 < TCH; t0 += 4) {
        unsigned long long a01 = bp, a23 = bp;
#pragma unroll
        for (int k = 0; k < II; k++) {
            ulonglong2 xv = *reinterpret_cast<const ulonglong2*>(&xt[k][t0]);
            a01 = fma2(ww[k], xv.x, a01);
            a23 = fma2(ww[k], xv.y, a23);
        }
        float g0, g1, g2, g3;
        unpack2(a01, g0, g1);
        unpack2(a23, g2, g3);

        float q0 = __shfl_down_sync(0xffffffffu, g0, 1);
        float q1 = __shfl_down_sync(0xffffffffu, g1, 1);
        float q2 = __shfl_down_sync(0xffffffffu, g2, 1);
        float q3 = __shfl_down_sync(0xffffffffu, g3, 1);
        if (writer) {
            uint32_t base = (uint32_t)(t0g + t0) * GX_TSTEP + inoff;
            *reinterpret_cast<uint32_t*>(gxb + base)                = pack_h2(g0, q0);
            *reinterpret_cast<uint32_t*>(gxb + base + GX_TSTEP)     = pack_h2(g1, q1);
            *reinterpret_cast<uint32_t*>(gxb + base + 2 * GX_TSTEP) = pack_h2(g2, q2);
            *reinterpret_cast<uint32_t*>(gxb + base + 3 * GX_TSTEP) = pack_h2(g3, q3);
        }
    }
}

// ============================================================
// Phase 2: recurrence via mma.sync fp16.
// grid 32, block 512 (16 warps). Warp w owns h-cols [8w, 8w+8)
// for all 3 gates: 24 MMAs/warp/step, dual accumulators (depth 4).
// ============================================================
__global__ __launch_bounds__(512, 1) void gru_rec(
    const float* __restrict__ Whh,   // [3H, H]
    const float* __restrict__ bhh,   // [3H]
    float* __restrict__ out)         // [B, H]
{
    const int tid  = threadIdx.x;
    const int w    = tid >> 5;       // 0..15
    const int lane = tid & 31;
    const int g    = lane >> 2;
    const int tig  = lane & 3;
    const int bg0  = blockIdx.x * MB;
    const int col  = w * 8 + 2 * tig;

    __shared__ __align__(16) __half h_sh[2][MB][HSTRIDE];

    // B fragments (W_hh) fp16: Bf[gate][ks][0/1]
    uint32_t Bf[3][8][2];
#pragma unroll
    for (int gate = 0; gate < 3; gate++) {
        const float* Wr = Whh + (size_t)(gate * HH + w * 8 + g) * HH;
#pragma unroll
        for (int ks = 0; ks < 8; ks++) {
            int c = ks * 16 + 2 * tig;
            float2 v0 = *reinterpret_cast<const float2*>(Wr + c);
            float2 v1 = *reinterpret_cast<const float2*>(Wr + c + 8);
            Bf[gate][ks][0] = pack_h2(v0.x, v0.y);
            Bf[gate][ks][1] = pack_h2(v1.x, v1.y);
        }
    }

    float bias[3][2];
#pragma unroll
    for (int gate = 0; gate < 3; gate++) {
        bias[gate][0] = bhh[gate * HH + col];
        bias[gate][1] = bhh[gate * HH + col + 1];
    }

    for (int i = tid; i < 2 * MB * HSTRIDE; i += 512)
        reinterpret_cast<__half*>(h_sh)[i] = __float2half(0.0f);

    const char* gxb = reinterpret_cast<const char*>(g_gx2);
    const uint32_t myoff = (uint32_t)(blockIdx.x * 6144 + w * 384 + lane * 4);

    uint32_t gcur[3];
#pragma unroll
    for (int p = 0; p < 3; p++)
        gcur[p] = *reinterpret_cast<const uint32_t*>(gxb + myoff + p * 128);

    float hp0 = 0.f, hp1 = 0.f;
    float hsum0 = 0.f, hsum1 = 0.f;

    const int arow  = lane & 7;
    const int ahalf = (lane >> 3) & 1;
    uint32_t hbase[2];
    hbase[0] = (uint32_t)__cvta_generic_to_shared(&h_sh[0][0][0]) +
               arow * (HSTRIDE * 2) + ahalf * 16;
    hbase[1] = (uint32_t)__cvta_generic_to_shared(&h_sh[1][0][0]) +
               arow * (HSTRIDE * 2) + ahalf * 16;

    __syncthreads();

    int cur = 0;
    for (int t = 0; t < TT; t++) {
        // prefetch next step's gx (3 coalesced LDG.32)
        uint32_t gnxt[3];
        if (t + 1 < TT) {
            const char* p = gxb + (size_t)(t + 1) * GX_TSTEP + myoff;
            gnxt[0] = *reinterpret_cast<const uint32_t*>(p);
            gnxt[1] = *reinterpret_cast<const uint32_t*>(p + 128);
            gnxt[2] = *reinterpret_cast<const uint32_t*>(p + 256);
        } else {
            gnxt[0] = gnxt[1] = gnxt[2] = 0u;
        }

        uint32_t A0[8], A2[8];
#pragma unroll
        for (int ks = 0; ks < 8; ks++)
            ldsm_x2(A0[ks], A2[ks], hbase[cur] + ks * 32);

        // 3 gates x dual accumulators (depth-4 chains)
        float D[3][2];
#pragma unroll
        for (int gate = 0; gate < 3; gate++) {
            float e0 = 0.f, e1 = 0.f, e2 = 0.f, e3 = 0.f;   // even ks
            float o0 = 0.f, o1 = 0.f, o2 = 0.f, o3 = 0.f;   // odd ks
#pragma unroll
            for (int ks = 0; ks < 8; ks += 2) {
                mma_f16(e0, e1, e2, e3, A0[ks], 0u, A2[ks], 0u,
                        Bf[gate][ks][0], Bf[gate][ks][1], e0, e1, e2, e3);
                mma_f16(o0, o1, o2, o3, A0[ks + 1], 0u, A2[ks + 1], 0u,
                        Bf[gate][ks + 1][0], Bf[gate][ks + 1][1], o0, o1, o2, o3);
            }
            D[gate][0] = e0 + o0;
            D[gate][1] = e1 + o1;
        }

        // epilogue (registers only)
        {
            uint32_t wr = gcur[0], wz = gcur[1], wn = gcur[2];
            float rr0 = sigmoid_ap(D[0][0] + bias[0][0] + h2_lo(wr));
            float rr1 = sigmoid_ap(D[0][1] + bias[0][1] + h2_hi(wr));
            float zz0 = sigmoid_ap(D[1][0] + bias[1][0] + h2_lo(wz));
            float zz1 = sigmoid_ap(D[1][1] + bias[1][1] + h2_hi(wz));
            float nn0 = tanh_ap(fmaf(rr0, D[2][0] + bias[2][0], h2_lo(wn)));
            float nn1 = tanh_ap(fmaf(rr1, D[2][1] + bias[2][1], h2_hi(wn)));

            float h0 = fmaf(zz0, hp0 - nn0, nn0);
            float h1 = fmaf(zz1, hp1 - nn1, nn1);
            *reinterpret_cast<uint32_t*>(&h_sh[cur ^ 1][g][col]) = pack_h2(h0, h1);
            hp0 = h0;  hp1 = h1;
            hsum0 += h0;  hsum1 += h1;
        }

        __syncthreads();
        cur ^= 1;
        gcur[0] = gnxt[0];  gcur[1] = gnxt[1];  gcur[2] = gnxt[2];
    }

    out[(bg0 + g) * HH + col]     = hsum0 * (1.0f / (float)TT);
    out[(bg0 + g) * HH + col + 1] = hsum1 * (1.0f / (float)TT);
}

extern "C" void kernel_launch(void* const* d_in, const int* in_sizes, int n_in,
                              void* d_out, int out_size) {
    const float* x   = (const float*)d_in[0];
    const float* Wih = (const float*)d_in[1];
    const float* Whh = (const float*)d_in[2];
    const float* bih = (const float*)d_in[3];
    const float* bhh = (const float*)d_in[4];
    float* out = (float*)d_out;
    (void)in_sizes; (void)n_in; (void)out_size;

    gx_kernel<<<dim3(NCH, BB), G3>>>(x, Wih, bih);
    gru_rec<<<NREC_CTAS, 512>>>(Whh, bhh, out);
}

// round 9
// speedup vs baseline: 1.0467x; 1.0467x over previous
#include <cuda_runtime.h>
#include <cuda_fp16.h>
#include <cstdint>

#define BB 256
#define TT 2000
#define II 23
#define HH 128
#define G3 384
#define MB 8                   // batches per rec CTA
#define NREC_CTAS (BB / MB)    // 32
#define HSTRIDE 136            // padded fp16 h-row stride (272B)
#define TG 4                   // timesteps per gx block
#define SP 200                 // padded u32 stride per wp block in gx staging (200%32==8)

// gx scratch, FRAGMENT layout (8-warp rec mapping), fp16x2 words:
// byte(t, cta, warp, p, lane, wi) = t*196608 + cta*6144 + warp*768 + p*256 + lane*8 + wi*4
// w6 = tr*3+gate ; p = w6>>1 ; wi = w6&1 ; lane = g*4+tig ; halves=(col,col+1), col=(2w+tr)*8+2tig
#define GX_TSTEP 196608u
__device__ uint32_t g_gx2[(size_t)TT * NREC_CTAS * 1536];

// ---- helpers ----
__device__ __forceinline__ unsigned long long fma2(unsigned long long a,
                                                   unsigned long long b,
                                                   unsigned long long c) {
    unsigned long long d;
    asm("fma.rn.f32x2 %0, %1, %2, %3;" : "=l"(d) : "l"(a), "l"(b), "l"(c));
    return d;
}
__device__ __forceinline__ unsigned long long pack2(float lo, float hi) {
    unsigned long long d;
    asm("mov.b64 %0, {%1, %2};" : "=l"(d) : "f"(lo), "f"(hi));
    return d;
}
__device__ __forceinline__ void unpack2(unsigned long long v, float& lo, float& hi) {
    asm("mov.b64 {%0, %1}, %2;" : "=f"(lo), "=f"(hi) : "l"(v));
}
__device__ __forceinline__ float tanh_ap(float x) {
    float y;
    asm("tanh.approx.f32 %0, %1;" : "=f"(y) : "f"(x));
    return y;
}
__device__ __forceinline__ float sigmoid_ap(float x) {
    return fmaf(tanh_ap(0.5f * x), 0.5f, 0.5f);
}
__device__ __forceinline__ uint32_t pack_h2(float lo, float hi) {
    uint32_t d;
    asm("cvt.rn.f16x2.f32 %0, %1, %2;" : "=r"(d) : "f"(hi), "f"(lo));
    return d;
}
__device__ __forceinline__ float h2_lo(uint32_t v) {
    return __half2float(__low2half(*reinterpret_cast<const __half2*>(&v)));
}
__device__ __forceinline__ float h2_hi(uint32_t v) {
    return __half2float(__high2half(*reinterpret_cast<const __half2*>(&v)));
}
__device__ __forceinline__ void ldsm_x4(uint32_t& r0, uint32_t& r1, uint32_t& r2,
                                        uint32_t& r3, uint32_t addr) {
    asm volatile("ldmatrix.sync.aligned.m8n8.x4.shared.b16 {%0,%1,%2,%3}, [%4];"
                 : "=r"(r0), "=r"(r1), "=r"(r2), "=r"(r3) : "r"(addr));
}
__device__ __forceinline__ void mma_f16(float& d0, float& d1, float& d2, float& d3,
                                        uint32_t a0, uint32_t a1, uint32_t a2, uint32_t a3,
                                        uint32_t b0, uint32_t b1,
                                        float c0, float c1, float c2, float c3) {
    asm volatile(
        "mma.sync.aligned.m16n8k16.row.col.f32.f16.f16.f32 "
        "{%0,%1,%2,%3},{%4,%5,%6,%7},{%8,%9},{%10,%11,%12,%13};"
        : "=f"(d0), "=f"(d1), "=f"(d2), "=f"(d3)
        : "r"(a0), "r"(a1), "r"(a2), "r"(a3), "r"(b0), "r"(b1),
          "f"(c0), "f"(c1), "f"(c2), "f"(c3));
}

// ============================================================
// Phase 1: gx = W_ih.x + b_ih in fragment layout.
// Block = (4 timesteps) x (8 batches) -> stage in smem, then
// fully-coalesced 768B-segment copy-out (STG.128, 100% sectors).
// grid (TT/TG, NREC_CTAS), block 384.
// ============================================================
__global__ __launch_bounds__(G3) void gx_kernel(
    const float* __restrict__ x,
    const float* __restrict__ Wih,
    const float* __restrict__ bih)
{
    const int cta = blockIdx.y;          // batch group of 8
    const int t0g = blockIdx.x * TG;
    const int r   = threadIdx.x;

    __shared__ __align__(16) float    xs[MB][II][TG];     // 2.9 KB
    __shared__ __align__(16) uint32_t stage[TG][8][SP];   // 25.6 KB

    // load x[cta*8+g][t0g+t][k]
    for (int e = r; e < MB * TG * II; e += G3) {
        int g   = e / (TG * II);
        int rem = e - g * (TG * II);
        int t   = rem / II;
        int k   = rem - t * II;
        xs[g][k][t] = x[((size_t)(cta * MB + g) * TT + (t0g + t)) * II + k];
    }

    unsigned long long ww[II];
#pragma unroll
    for (int k = 0; k < II; k++) {
        float wv = Wih[r * II + k];
        ww[k] = pack2(wv, wv);
    }
    const float bv = bih[r];
    const unsigned long long bp = pack2(bv, bv);

    // fragment indices for row r
    const int gate = r >> 7;
    const int col  = r & 127;
    const int wp   = col >> 4;
    const int tr   = (col >> 3) & 1;
    const int tig  = (col & 7) >> 1;
    const int w6   = tr * 3 + gate;
    const int p    = w6 >> 1;
    const int wi   = w6 & 1;
    const bool writer = ((r & 1) == 0);

    __syncthreads();

#pragma unroll
    for (int g = 0; g < MB; g++) {
        unsigned long long a01 = bp, a23 = bp;
#pragma unroll
        for (int k = 0; k < II; k++) {
            ulonglong2 xv = *reinterpret_cast<const ulonglong2*>(&xs[g][k][0]);
            a01 = fma2(ww[k], xv.x, a01);
            a23 = fma2(ww[k], xv.y, a23);
        }
        float g0, g1, g2, g3;
        unpack2(a01, g0, g1);
        unpack2(a23, g2, g3);
        float q0 = __shfl_down_sync(0xffffffffu, g0, 1);
        float q1 = __shfl_down_sync(0xffffffffu, g1, 1);
        float q2 = __shfl_down_sync(0xffffffffu, g2, 1);
        float q3 = __shfl_down_sync(0xffffffffu, g3, 1);
        if (writer) {
            const int base = p * 64 + (g * 4 + tig) * 2 + wi;
            stage[0][wp][base] = pack_h2(g0, q0);
            stage[1][wp][base] = pack_h2(g1, q1);
            stage[2][wp][base] = pack_h2(g2, q2);
            stage[3][wp][base] = pack_h2(g3, q3);
        }
    }
    __syncthreads();

    // copy-out: 32 segments (t, wp) x 768B; thread handles 64B
    {
        const int seg = r / 12;          // 0..31
        const int l12 = r % 12;          // 0..11
        const int t   = seg >> 3;
        const int wp2 = seg & 7;
        const uint4* src = reinterpret_cast<const uint4*>(&stage[t][wp2][l12 * 16]);
        char* dst = reinterpret_cast<char*>(g_gx2) +
                    (size_t)(t0g + t) * GX_TSTEP + cta * 6144 + wp2 * 768 + l12 * 64;
        uint4 v0 = src[0], v1 = src[1], v2 = src[2], v3 = src[3];
        *reinterpret_cast<uint4*>(dst)      = v0;
        *reinterpret_cast<uint4*>(dst + 16) = v1;
        *reinterpret_cast<uint4*>(dst + 32) = v2;
        *reinterpret_cast<uint4*>(dst + 48) = v3;
    }
}

// ============================================================
// Phase 2: recurrence via mma.sync fp16 (R7 structure).
// grid 32, block 256 (8 warps). Warp w owns h-cols {2w,2w+1}*8
// for all 3 gates. Dual accumulators (depth 4), ldmatrix.x4.
// ============================================================
__global__ __launch_bounds__(256, 1) void gru_rec(
    const float* __restrict__ Whh,   // [3H, H]
    const float* __restrict__ bhh,   // [3H]
    float* __restrict__ out)         // [B, H]
{
    const int tid  = threadIdx.x;
    const int w    = tid >> 5;
    const int lane = tid & 31;
    const int g    = lane >> 2;
    const int tig  = lane & 3;
    const int bg0  = blockIdx.x * MB;

    __shared__ __align__(16) __half h_sh[2][MB][HSTRIDE];

    uint32_t Bf[2][3][8][2];
#pragma unroll
    for (int tr = 0; tr < 2; tr++) {
        const int cg = 2 * w + tr;
#pragma unroll
        for (int gate = 0; gate < 3; gate++) {
            const float* Wr = Whh + (size_t)(gate * HH + cg * 8 + g) * HH;
#pragma unroll
            for (int ks = 0; ks < 8; ks++) {
                int c = ks * 16 + 2 * tig;
                float2 v0 = *reinterpret_cast<const float2*>(Wr + c);
                float2 v1 = *reinterpret_cast<const float2*>(Wr + c + 8);
                Bf[tr][gate][ks][0] = pack_h2(v0.x, v0.y);
                Bf[tr][gate][ks][1] = pack_h2(v1.x, v1.y);
            }
        }
    }

    float bias[2][3][2];
#pragma unroll
    for (int tr = 0; tr < 2; tr++) {
        const int col = (2 * w + tr) * 8 + 2 * tig;
#pragma unroll
        for (int gate = 0; gate < 3; gate++) {
            bias[tr][gate][0] = bhh[gate * HH + col];
            bias[tr][gate][1] = bhh[gate * HH + col + 1];
        }
    }

    for (int i = tid; i < 2 * MB * HSTRIDE; i += 256)
        reinterpret_cast<__half*>(h_sh)[i] = __float2half(0.0f);

    const char* gxb = reinterpret_cast<const char*>(g_gx2);
    const uint32_t myoff = (uint32_t)(blockIdx.x * 6144 + w * 768 + lane * 8);

    uint2 gcur[3];
#pragma unroll
    for (int p = 0; p < 3; p++)
        gcur[p] = *reinterpret_cast<const uint2*>(gxb + myoff + p * 256);

    float hp[2][2]   = {{0.f, 0.f}, {0.f, 0.f}};
    float hsum[2][2] = {{0.f, 0.f}, {0.f, 0.f}};

    // ldmatrix.x4 addressing: matrices (ks,h0),(ks,h1),(ks+1,h0),(ks+1,h1)
    const int arow = lane & 7;
    const uint32_t hoff = arow * (HSTRIDE * 2) + ((lane >> 3) & 1) * 16 +
                          (lane >> 4) * 32;
    uint32_t hbase[2];
    hbase[0] = (uint32_t)__cvta_generic_to_shared(&h_sh[0][0][0]) + hoff;
    hbase[1] = (uint32_t)__cvta_generic_to_shared(&h_sh[1][0][0]) + hoff;

    __syncthreads();

    int cur = 0;
    for (int t = 0; t < TT; t++) {
        uint2 gnxt[3];
        if (t + 1 < TT) {
            const char* p = gxb + (size_t)(t + 1) * GX_TSTEP + myoff;
            gnxt[0] = *reinterpret_cast<const uint2*>(p);
            gnxt[1] = *reinterpret_cast<const uint2*>(p + 256);
            gnxt[2] = *reinterpret_cast<const uint2*>(p + 512);
        } else {
            gnxt[0] = gnxt[1] = gnxt[2] = make_uint2(0u, 0u);
        }

        uint32_t A0[8], A2[8];
#pragma unroll
        for (int kp = 0; kp < 4; kp++)
            ldsm_x4(A0[2 * kp], A2[2 * kp], A0[2 * kp + 1], A2[2 * kp + 1],
                    hbase[cur] + kp * 64);

        float D[2][3][2];
#pragma unroll
        for (int tr = 0; tr < 2; tr++)
#pragma unroll
            for (int gate = 0; gate < 3; gate++) {
                float e0 = 0.f, e1 = 0.f, e2 = 0.f, e3 = 0.f;
                float o0 = 0.f, o1 = 0.f, o2 = 0.f, o3 = 0.f;
#pragma unroll
                for (int ks = 0; ks < 8; ks += 2) {
                    mma_f16(e0, e1, e2, e3, A0[ks], 0u, A2[ks], 0u,
                            Bf[tr][gate][ks][0], Bf[tr][gate][ks][1],
                            e0, e1, e2, e3);
                    mma_f16(o0, o1, o2, o3, A0[ks + 1], 0u, A2[ks + 1], 0u,
                            Bf[tr][gate][ks + 1][0], Bf[tr][gate][ks + 1][1],
                            o0, o1, o2, o3);
                }
                D[tr][gate][0] = e0 + o0;
                D[tr][gate][1] = e1 + o1;
            }

        // epilogue (registers only). w6 = tr*3+gate -> gcur[w6>>1].x/.y
#pragma unroll
        for (int tr = 0; tr < 2; tr++) {
            uint32_t wr = (tr == 0) ? gcur[0].x : gcur[1].y;
            uint32_t wz = (tr == 0) ? gcur[0].y : gcur[2].x;
            uint32_t wn = (tr == 0) ? gcur[1].x : gcur[2].y;

            float rr0 = sigmoid_ap(D[tr][0][0] + bias[tr][0][0] + h2_lo(wr));
            float rr1 = sigmoid_ap(D[tr][0][1] + bias[tr][0][1] + h2_hi(wr));
            float zz0 = sigmoid_ap(D[tr][1][0] + bias[tr][1][0] + h2_lo(wz));
            float zz1 = sigmoid_ap(D[tr][1][1] + bias[tr][1][1] + h2_hi(wz));
            float nn0 = tanh_ap(fmaf(rr0, D[tr][2][0] + bias[tr][2][0], h2_lo(wn)));
            float nn1 = tanh_ap(fmaf(rr1, D[tr][2][1] + bias[tr][2][1], h2_hi(wn)));

            float h0 = fmaf(zz0, hp[tr][0] - nn0, nn0);
            float h1 = fmaf(zz1, hp[tr][1] - nn1, nn1);
            hp[tr][0] = h0;  hp[tr][1] = h1;
            hsum[tr][0] += h0;  hsum[tr][1] += h1;

            const int col = (2 * w + tr) * 8 + 2 * tig;
            *reinterpret_cast<uint32_t*>(&h_sh[cur ^ 1][g][col]) = pack_h2(h0, h1);
        }

        __syncthreads();
        cur ^= 1;
        gcur[0] = gnxt[0];  gcur[1] = gnxt[1];  gcur[2] = gnxt[2];
    }

#pragma unroll
    for (int tr = 0; tr < 2; tr++) {
        const int col = (2 * w + tr) * 8 + 2 * tig;
        out[(bg0 + g) * HH + col]     = hsum[tr][0] * (1.0f / (float)TT);
        out[(bg0 + g) * HH + col + 1] = hsum[tr][1] * (1.0f / (float)TT);
    }
}

extern "C" void kernel_launch(void* const* d_in, const int* in_sizes, int n_in,
                              void* d_out, int out_size) {
    const float* x   = (const float*)d_in[0];
    const float* Wih = (const float*)d_in[1];
    const float* Whh = (const float*)d_in[2];
    const float* bih = (const float*)d_in[3];
    const float* bhh = (const float*)d_in[4];
    float* out = (float*)d_out;
    (void)in_sizes; (void)n_in; (void)out_size;

    gx_kernel<<<dim3(TT / TG, NREC_CTAS), G3>>>(x, Wih, bih);
    gru_rec<<<NREC_CTAS, 256>>>(Whh, bhh, out);
}

// round 11
// speedup vs baseline: 1.4032x; 1.3407x over previous
#include <cuda_runtime.h>
#include <cuda_fp16.h>
#include <cstdint>

#define BB 256
#define TT 2000
#define II 23
#define HH 128
#define MB 8                    // batches per CTA
#define NREC_CTAS (BB / MB)     // 32
#define KK 160                  // concatenated K: 128 h + 32 x (23 real + 9 zero)
#define NSL 10                  // k-slices of 16
#define HSTRIDE 168             // padded fp16 row stride (336B; conflict-free ldsm)

__device__ __forceinline__ float tanh_ap(float x) {
    float y;
    asm("tanh.approx.f32 %0, %1;" : "=f"(y) : "f"(x));
    return y;
}
__device__ __forceinline__ float sigmoid_ap(float x) {
    return fmaf(tanh_ap(0.5f * x), 0.5f, 0.5f);
}
__device__ __forceinline__ uint32_t pack_h2(float lo, float hi) {
    uint32_t d;
    asm("cvt.rn.f16x2.f32 %0, %1, %2;" : "=r"(d) : "f"(hi), "f"(lo));
    return d;
}
__device__ __forceinline__ void ldsm_x2(uint32_t& r0, uint32_t& r1, uint32_t addr) {
    asm volatile("ldmatrix.sync.aligned.m8n8.x2.shared.b16 {%0,%1}, [%2];"
                 : "=r"(r0), "=r"(r1) : "r"(addr));
}
__device__ __forceinline__ void mma_f16(float& d0, float& d1, float& d2, float& d3,
                                        uint32_t a0, uint32_t a1, uint32_t a2, uint32_t a3,
                                        uint32_t b0, uint32_t b1,
                                        float c0, float c1, float c2, float c3) {
    asm volatile(
        "mma.sync.aligned.m16n8k16.row.col.f32.f16.f16.f32 "
        "{%0,%1,%2,%3},{%4,%5,%6,%7},{%8,%9},{%10,%11,%12,%13};"
        : "=f"(d0), "=f"(d1), "=f"(d2), "=f"(d3)
        : "r"(a0), "r"(a1), "r"(a2), "r"(a3), "r"(b0), "r"(b1),
          "f"(c0), "f"(c1), "f"(c2), "f"(c3));
}

// ============================================================
// Fused GRU: grid 32, block 256 (8 warps), 8 batches/CTA.
// K-concatenated MMA: gate = [W_hh | W_ih] . [h ; x(t)].
// Warp w owns output cols {2w, 2w+1}*8 for all 3 gates.
// Gates r,z: one 10-slice chain. Gate n: h-chain (8) + x-chain (2).
// h & x double-buffered fp16 in smem; one barrier per step.
// ============================================================
__global__ __launch_bounds__(256, 1) void gru_fused(
    const float* __restrict__ x,     // [B, T, I]
    const float* __restrict__ Wih,   // [3H, I]
    const float* __restrict__ Whh,   // [3H, H]
    const float* __restrict__ bih,   // [3H]
    const float* __restrict__ bhh,   // [3H]
    float* __restrict__ out)         // [B, H]
{
    const int tid  = threadIdx.x;
    const int w    = tid >> 5;
    const int lane = tid & 31;
    const int g    = lane >> 2;
    const int tig  = lane & 3;
    const int bg0  = blockIdx.x * MB;

    __shared__ __align__(16) __half h_sh[2][MB][HSTRIDE];

    // ---- B fragments: slices 0..7 from W_hh, 8..9 from W_ih (zero-padded) ----
    uint32_t Bf[2][3][NSL][2];
#pragma unroll
    for (int tr = 0; tr < 2; tr++) {
        const int cg = 2 * w + tr;
#pragma unroll
        for (int gate = 0; gate < 3; gate++) {
            const int orow = gate * HH + cg * 8 + g;
            const float* WrH = Whh + (size_t)orow * HH;
#pragma unroll
            for (int ks = 0; ks < 8; ks++) {
                int c = ks * 16 + 2 * tig;
                float2 v0 = *reinterpret_cast<const float2*>(WrH + c);
                float2 v1 = *reinterpret_cast<const float2*>(WrH + c + 8);
                Bf[tr][gate][ks][0] = pack_h2(v0.x, v0.y);
                Bf[tr][gate][ks][1] = pack_h2(v1.x, v1.y);
            }
            const float* WrI = Wih + (size_t)orow * II;
#pragma unroll
            for (int s = 0; s < 2; s++) {
                int c = s * 16 + 2 * tig;
                float e0 = (c     < II) ? WrI[c]     : 0.f;
                float e1 = (c + 1 < II) ? WrI[c + 1] : 0.f;
                float e2 = (c + 8 < II) ? WrI[c + 8] : 0.f;
                float e3 = (c + 9 < II) ? WrI[c + 9] : 0.f;
                Bf[tr][gate][8 + s][0] = pack_h2(e0, e1);
                Bf[tr][gate][8 + s][1] = pack_h2(e2, e3);
            }
        }
    }

    // ---- biases: r,z folded (bih+bhh); n kept separate ----
    float bs_r[2][2], bs_z[2][2], bh_n[2][2], bi_n[2][2];
#pragma unroll
    for (int tr = 0; tr < 2; tr++) {
        const int col = (2 * w + tr) * 8 + 2 * tig;
        bs_r[tr][0] = bih[col] + bhh[col];
        bs_r[tr][1] = bih[col + 1] + bhh[col + 1];
        bs_z[tr][0] = bih[HH + col] + bhh[HH + col];
        bs_z[tr][1] = bih[HH + col + 1] + bhh[HH + col + 1];
        bh_n[tr][0] = bhh[2 * HH + col];
        bh_n[tr][1] = bhh[2 * HH + col + 1];
        bi_n[tr][0] = bih[2 * HH + col];
        bi_n[tr][1] = bih[2 * HH + col + 1];
    }

    // zero both buffers (h=0; x region + tail pad = 0)
    for (int i = tid; i < 2 * MB * HSTRIDE; i += 256)
        reinterpret_cast<__half*>(h_sh)[i] = __float2half(0.0f);

    // x staging role: threads 0..95 -> (batch xb, word xj), 12 f16x2 words/batch
    const int xb = tid / 12;       // 0..7 (for tid<96)
    const int xj = tid % 12;       // 0..11 ; word covers x[2j], x[2j+1]
    const bool xrole = (tid < 96);
    const float* xrow_base = x + (size_t)(bg0 + (xrole ? xb : 0)) * TT * II;

    __syncthreads();   // after zeroing, before staging x[0]

    // stage x[t=0] into buffer 0 (SCALAR loads: x rows are only 4B-aligned)
    if (xrole) {
        const float* xr = xrow_base;   // t = 0
        float e0 = xr[2 * xj];
        float e1 = (2 * xj + 1 < II) ? xr[2 * xj + 1] : 0.f;
        *reinterpret_cast<uint32_t*>(&h_sh[0][xb][HH + 2 * xj]) = pack_h2(e0, e1);
    }

    float hp[2][2]   = {{0.f, 0.f}, {0.f, 0.f}};
    float hsum[2][2] = {{0.f, 0.f}, {0.f, 0.f}};

    const int arow  = lane & 7;
    const int ahalf = (lane >> 3) & 1;
    uint32_t hbase[2];
    hbase[0] = (uint32_t)__cvta_generic_to_shared(&h_sh[0][0][0]) +
               arow * (HSTRIDE * 2) + ahalf * 16;
    hbase[1] = (uint32_t)__cvta_generic_to_shared(&h_sh[1][0][0]) +
               arow * (HSTRIDE * 2) + ahalf * 16;

    __syncthreads();

    int cur = 0;
    for (int t = 0; t < TT; t++) {
        // prefetch x[t+1] (threads 0..95): scalar LDGs issued early
        uint32_t xw = 0u;
        const bool xdo = xrole && (t + 1 < TT);
        if (xdo) {
            const float* xr = xrow_base + (size_t)(t + 1) * II;
            float e0 = xr[2 * xj];
            float e1 = (2 * xj + 1 < II) ? xr[2 * xj + 1] : 0.f;
            xw = pack_h2(e0, e1);
        }

        // A fragments: 10 k-slices of [h ; x]
        uint32_t A0[NSL], A2[NSL];
#pragma unroll
        for (int ks = 0; ks < NSL; ks++)
            ldsm_x2(A0[ks], A2[ks], hbase[cur] + ks * 32);

        // ---- MMA chains ----
        float Dr[2][2], Dz[2][2], Dnh[2][2], Dnx[2][2];
#pragma unroll
        for (int tr = 0; tr < 2; tr++) {
            // gate r: 10 slices, one chain
            {
                float d0 = 0.f, d1 = 0.f, d2 = 0.f, d3 = 0.f;
#pragma unroll
                for (int ks = 0; ks < NSL; ks++)
                    mma_f16(d0, d1, d2, d3, A0[ks], 0u, A2[ks], 0u,
                            Bf[tr][0][ks][0], Bf[tr][0][ks][1], d0, d1, d2, d3);
                Dr[tr][0] = d0; Dr[tr][1] = d1;
            }
            // gate z: 10 slices
            {
                float d0 = 0.f, d1 = 0.f, d2 = 0.f, d3 = 0.f;
#pragma unroll
                for (int ks = 0; ks < NSL; ks++)
                    mma_f16(d0, d1, d2, d3, A0[ks], 0u, A2[ks], 0u,
                            Bf[tr][1][ks][0], Bf[tr][1][ks][1], d0, d1, d2, d3);
                Dz[tr][0] = d0; Dz[tr][1] = d1;
            }
            // gate n: h part (slices 0..7) and x part (8..9) separate
            {
                float d0 = 0.f, d1 = 0.f, d2 = 0.f, d3 = 0.f;
#pragma unroll
                for (int ks = 0; ks < 8; ks++)
                    mma_f16(d0, d1, d2, d3, A0[ks], 0u, A2[ks], 0u,
                            Bf[tr][2][ks][0], Bf[tr][2][ks][1], d0, d1, d2, d3);
                Dnh[tr][0] = d0; Dnh[tr][1] = d1;
                float f0 = 0.f, f1 = 0.f, f2 = 0.f, f3 = 0.f;
#pragma unroll
                for (int ks = 8; ks < NSL; ks++)
                    mma_f16(f0, f1, f2, f3, A0[ks], 0u, A2[ks], 0u,
                            Bf[tr][2][ks][0], Bf[tr][2][ks][1], f0, f1, f2, f3);
                Dnx[tr][0] = f0; Dnx[tr][1] = f1;
            }
        }

        // ---- epilogue (registers only) ----
#pragma unroll
        for (int tr = 0; tr < 2; tr++) {
            float rr0 = sigmoid_ap(Dr[tr][0] + bs_r[tr][0]);
            float rr1 = sigmoid_ap(Dr[tr][1] + bs_r[tr][1]);
            float zz0 = sigmoid_ap(Dz[tr][0] + bs_z[tr][0]);
            float zz1 = sigmoid_ap(Dz[tr][1] + bs_z[tr][1]);
            float nn0 = tanh_ap(fmaf(rr0, Dnh[tr][0] + bh_n[tr][0],
                                     Dnx[tr][0] + bi_n[tr][0]));
            float nn1 = tanh_ap(fmaf(rr1, Dnh[tr][1] + bh_n[tr][1],
                                     Dnx[tr][1] + bi_n[tr][1]));

            float h0 = fmaf(zz0, hp[tr][0] - nn0, nn0);
            float h1 = fmaf(zz1, hp[tr][1] - nn1, nn1);
            hp[tr][0] = h0;  hp[tr][1] = h1;
            hsum[tr][0] += h0;  hsum[tr][1] += h1;

            const int col = (2 * w + tr) * 8 + 2 * tig;
            *reinterpret_cast<uint32_t*>(&h_sh[cur ^ 1][g][col]) = pack_h2(h0, h1);
        }

        // stage x[t+1] into the next buffer
        if (xdo)
            *reinterpret_cast<uint32_t*>(&h_sh[cur ^ 1][xb][HH + 2 * xj]) = xw;

        __syncthreads();
        cur ^= 1;
    }

#pragma unroll
    for (int tr = 0; tr < 2; tr++) {
        const int col = (2 * w + tr) * 8 + 2 * tig;
        out[(bg0 + g) * HH + col]     = hsum[tr][0] * (1.0f / (float)TT);
        out[(bg0 + g) * HH + col + 1] = hsum[tr][1] * (1.0f / (float)TT);
    }
}

extern "C" void kernel_launch(void* const* d_in, const int* in_sizes, int n_in,
                              void* d_out, int out_size) {
    const float* x   = (const float*)d_in[0];
    const float* Wih = (const float*)d_in[1];
    const float* Whh = (const float*)d_in[2];
    const float* bih = (const float*)d_in[3];
    const float* bhh = (const float*)d_in[4];
    float* out = (float*)d_out;
    (void)in_sizes; (void)n_in; (void)out_size;

    gru_fused<<<NREC_CTAS, 256>>>(x, Wih, Whh, bih, bhh, out);
}